// round 8
// baseline (speedup 1.0000x reference)
#include <cuda_runtime.h>
#include <math.h>

#define N_ 64
#define C_ 64
#define T_ 300
#define V_ 25
#define S_ 3
#define I_ 16
#define TV_ 7500
#define KIT_ 4800
#define NTV_ 480000.0

// ---------------- scratch ----------------
__device__ __align__(16) unsigned g_Wt[96 * 64];      // wa/wb packed, tf32 bits
__device__ __align__(16) unsigned g_WdTt[192 * 64];   // wdT: [(s*64+c)*64+o], tf32 bits
__device__ float g_bias[96];
__device__ float g_bdsum[64];
__device__ __align__(16) float g_a[(size_t)N_ * 48 * TV_];
__device__ __align__(16) float g_b[(size_t)N_ * 48 * TV_];
__device__ float g_psc[3 * 64 * 5 * 676];
__device__ float g_adapt[N_ * S_ * V_ * V_];
__device__ __align__(16) float g_y[(size_t)N_ * C_ * TV_];
__device__ float g_pb[4800 * 128];                    // per-block, per-channel {s1,s2}
__device__ float g_scale[64];
__device__ float g_shift[64];

__device__ __forceinline__ unsigned f2tf32(float f) {
    unsigned u; asm("cvt.rna.tf32.f32 %0, %1;" : "=r"(u) : "f"(f)); return u;
}
__device__ __forceinline__ void mma8(float* d, const unsigned* a, const unsigned* b) {
    asm volatile("mma.sync.aligned.m16n8k8.row.col.f32.tf32.tf32.f32 "
        "{%0,%1,%2,%3}, {%4,%5,%6,%7}, {%8,%9}, {%0,%1,%2,%3};"
        : "+f"(d[0]), "+f"(d[1]), "+f"(d[2]), "+f"(d[3])
        : "r"(a[0]), "r"(a[1]), "r"(a[2]), "r"(a[3]), "r"(b[0]), "r"(b[1]));
}

// ---------------- K0: pack ----------------
__global__ void k0_pack(const float* __restrict__ wa, const float* __restrict__ ba,
                        const float* __restrict__ wb, const float* __restrict__ bb,
                        const float* __restrict__ wd, const float* __restrict__ bd) {
    int idx = blockIdx.x * 256 + threadIdx.x;
    if (idx < 96 * 64) {
        int row = idx / 64, k = idx % 64;
        float v = (row < 48) ? wa[row * 64 + k] : wb[(row - 48) * 64 + k];
        g_Wt[idx] = f2tf32(v);
    } else if (idx < 96 * 64 + 192 * 64) {
        int j = idx - 96 * 64;
        int s = j / 4096, r = j % 4096;
        int c = r >> 6, o = r & 63;
        g_WdTt[j] = f2tf32(wd[(s * 64 + o) * 64 + c]);
    } else if (idx < 96 * 64 + 192 * 64 + 96) {
        int row = idx - (96 * 64 + 192 * 64);
        g_bias[row] = (row < 48) ? ba[row] : bb[row - 48];
    } else if (idx < 96 * 64 + 192 * 64 + 96 + 64) {
        int o = idx - (96 * 64 + 192 * 64 + 96);
        g_bdsum[o] = bd[o] + bd[64 + o] + bd[128 + o];
    }
}

// ---------------- KG: tf32 GEMM [96,64]@[64,7500] per n (a,b only) ----------------
#define PM 104
#define PN 136

__global__ __launch_bounds__(256) void kg_tf32(const float* __restrict__ x) {
    __shared__ __align__(16) unsigned As[32 * PM];
    __shared__ __align__(16) unsigned Bs[32 * PN];
    const int n = blockIdx.z;
    const int rowBase = 0;
    const int col0 = blockIdx.y * 128;
    const int t = threadIdx.x;
    const int warp = t >> 5, lane = t & 31;
    const int g = lane >> 2, tig = lane & 3;
    const int wm = warp >> 2, wn = warp & 3;
    const int mBase0 = wm * 48, nBase0 = wn * 32;
    const float* xn = x + (size_t)n * (C_ * TV_);

    float acc[3][4][4];
#pragma unroll
    for (int mt = 0; mt < 3; mt++)
#pragma unroll
        for (int nt = 0; nt < 4; nt++)
#pragma unroll
            for (int q = 0; q < 4; q++) acc[mt][nt][q] = 0.0f;

    for (int phase = 0; phase < 2; phase++) {
        const int kb0 = phase * 32;
#pragma unroll
        for (int it = 0; it < 3; it++) {
            int idx = it * 256 + t;
            int m = idx % 96;
            int kq = idx / 96;
            uint4 w4 = *(const uint4*)(g_Wt + (rowBase + m) * 64 + kb0 + kq * 4);
            As[(kq * 4 + 0) * PM + m] = w4.x;
            As[(kq * 4 + 1) * PM + m] = w4.y;
            As[(kq * 4 + 2) * PM + m] = w4.z;
            As[(kq * 4 + 3) * PM + m] = w4.w;
        }
#pragma unroll
        for (int it = 0; it < 4; it++) {
            int idx = it * 256 + t;
            int k = idx >> 5;
            int c4 = (idx & 31) * 4;
            int col = col0 + c4;
            float4 v = make_float4(0.f, 0.f, 0.f, 0.f);
            if (col + 3 < TV_)
                v = *(const float4*)(xn + (size_t)(kb0 + k) * TV_ + col);
            unsigned* dst = &Bs[k * PN + c4];
            dst[0] = f2tf32(v.x); dst[1] = f2tf32(v.y);
            dst[2] = f2tf32(v.z); dst[3] = f2tf32(v.w);
        }
        __syncthreads();
#pragma unroll
        for (int ks = 0; ks < 4; ks++) {
            const int kb = ks * 8;
            unsigned a[3][4], b[4][2];
#pragma unroll
            for (int mt = 0; mt < 3; mt++) {
                int mB = mBase0 + mt * 16;
                a[mt][0] = As[(kb + tig) * PM + mB + g];
                a[mt][1] = As[(kb + tig) * PM + mB + g + 8];
                a[mt][2] = As[(kb + tig + 4) * PM + mB + g];
                a[mt][3] = As[(kb + tig + 4) * PM + mB + g + 8];
            }
#pragma unroll
            for (int nt = 0; nt < 4; nt++) {
                int nB = nBase0 + nt * 8;
                b[nt][0] = Bs[(kb + tig) * PN + nB + g];
                b[nt][1] = Bs[(kb + tig + 4) * PN + nB + g];
            }
#pragma unroll
            for (int mt = 0; mt < 3; mt++)
#pragma unroll
                for (int nt = 0; nt < 4; nt++)
                    mma8(acc[mt][nt], a[mt], b[nt]);
        }
        __syncthreads();
    }

#pragma unroll
    for (int mt = 0; mt < 3; mt++) {
#pragma unroll
        for (int h = 0; h < 2; h++) {
            int gm = rowBase + mBase0 + mt * 16 + g + h * 8;
            float bias = g_bias[gm];
            float* dst = (gm < 48) ? (g_a + ((size_t)n * 48 + gm) * TV_)
                                   : (g_b + ((size_t)n * 48 + (gm - 48)) * TV_);
#pragma unroll
            for (int nt = 0; nt < 4; nt++) {
                int col = col0 + nBase0 + nt * 8 + tig * 2;
                if (col < TV_) {
                    float2 v = make_float2(acc[mt][nt][h * 2 + 0] + bias,
                                           acc[mt][nt][h * 2 + 1] + bias);
                    *(float2*)(dst + col) = v;
                }
            }
        }
    }
}

// ---------------- K2a: partial scores (validated) ----------------
#define K2W 28
__global__ __launch_bounds__(256) void k2a() {
    __shared__ __align__(16) float ach[64 * K2W];
    __shared__ __align__(16) float bch[64 * K2W];
    const int s = blockIdx.x, n = blockIdx.y, q = blockIdx.z;
    const int tid = threadIdx.x;
    const float* abase = g_a + ((size_t)n * 48 + s * 16) * TV_;
    const float* bbase = g_b + ((size_t)n * 48 + s * 16) * TV_;
    const int tv = tid / 13, tw = tid % 13;
    const bool act = (tid < 169);
    const int v0 = 2 * tv, w0 = 2 * tw;
    float acc00 = 0.f, acc01 = 0.f, acc10 = 0.f, acc11 = 0.f;

    for (int c = q * 15; c < q * 15 + 15; c++) {
        __syncthreads();
        for (int idx = tid; idx < 64 * 26; idx += 256) {
            int kk = idx / 26, vv = idx % 26;
            int k = c * 64 + kk;
            int i = k / 300, tt = k % 300;
            float av = 0.f, bv = 0.f;
            if (vv < 25) {
                size_t off = (size_t)i * TV_ + tt * 25 + vv;
                av = abase[off]; bv = bbase[off];
            }
            ach[kk * K2W + vv] = av;
            bch[kk * K2W + vv] = bv;
        }
        __syncthreads();
        if (act) {
#pragma unroll 8
            for (int kk = 0; kk < 64; kk++) {
                float2 a2 = *(const float2*)&ach[kk * K2W + v0];
                float2 b2 = *(const float2*)&bch[kk * K2W + w0];
                acc00 = fmaf(a2.x, b2.x, acc00);
                acc01 = fmaf(a2.x, b2.y, acc01);
                acc10 = fmaf(a2.y, b2.x, acc10);
                acc11 = fmaf(a2.y, b2.y, acc11);
            }
        }
    }
    if (act) {
        float* dst = g_psc + ((size_t)(s * 64 + n) * 5 + q) * 676;
        dst[v0 * 26 + w0]           = acc00;
        dst[v0 * 26 + w0 + 1]       = acc01;
        dst[(v0 + 1) * 26 + w0]     = acc10;
        dst[(v0 + 1) * 26 + w0 + 1] = acc11;
    }
}

// ---------------- K2b: combine + softmax + adapt (validated) ----------------
__global__ __launch_bounds__(640) void k2b(const float* __restrict__ Aad,
                                           const float* __restrict__ Wad) {
    __shared__ float ssc[25][26];
    __shared__ float smax[25];
    __shared__ float ssum[25];
    const int s = blockIdx.x, n = blockIdx.y;
    const int tid = threadIdx.x;
    const int v = tid / 25, w = tid % 25;
    const float* base = g_psc + (size_t)(s * 64 + n) * 5 * 676;

    if (tid < 625) {
        float sum = base[v * 26 + w];
        sum += base[676 + v * 26 + w];
        sum += base[2 * 676 + v * 26 + w];
        sum += base[3 * 676 + v * 26 + w];
        sum += base[4 * 676 + v * 26 + w];
        ssc[v][w] = sum * (1.0f / (float)KIT_);
    }
    __syncthreads();
    if (tid < 25) {
        float m = -1e30f;
        for (int vv = 0; vv < 25; vv++) m = fmaxf(m, ssc[vv][tid]);
        smax[tid] = m;
    }
    __syncthreads();
    if (tid < 625) ssc[v][w] = expf(ssc[v][w] - smax[w]);
    __syncthreads();
    if (tid < 25) {
        float sum = 0.0f;
        for (int vv = 0; vv < 25; vv++) sum += ssc[vv][tid];
        ssum[tid] = sum;
    }
    __syncthreads();
    if (tid < 625) {
        int aw = (s * 25 + v) * 25 + w;
        g_adapt[((n * 3 + s) * 25 + v) * 25 + w] = Aad[aw] + Wad[aw] + ssc[v][w] / ssum[w];
    }
}

// ---------------- K45: fused y = sum_s wdT_s @ (x @ adapt_s) + bd, BN partials ----------------
// block = (n, 4 t's). stage1: M=256 rows (c*4+t), N=32(w), K=32(v)  [k4 pattern]
//                     stage2: M=64(o), N=128((t,w) pad), K=64(c)     [kg pattern]
struct SmemK45 {
    unsigned xs[256 * 36];   // stage1 A: [m=(c*4+tl)][k=v]
    unsigned xa[64 * 128];   // stage1 out / stage2 B: [k=c][n=tl*25+w]; aliased as ys
    unsigned ads[32 * 40];   // stage1 B: [k=v][n=w]
    unsigned wdt[64 * 72];   // stage2 A: [k=c][m=o]
    float rb1[256];
    float rb2[256];
};

__global__ __launch_bounds__(256) void k45(const float* __restrict__ x) {
    extern __shared__ __align__(16) unsigned char smraw[];
    SmemK45* sm = (SmemK45*)smraw;
    const int bi = blockIdx.x;
    const int n = bi / 75;
    const int t0 = (bi % 75) * 4;
    const int tid = threadIdx.x, warp = tid >> 5, lane = tid & 31;
    const int g = lane >> 2, tig = lane & 3;
    const int mA0 = warp * 32;                  // stage1 warp rows
    const int mB0 = (warp >> 2) * 32;           // stage2: o base
    const int nB0 = (warp & 3) * 32;            // stage2: col base

    float acc2[2][4][4];
#pragma unroll
    for (int mt = 0; mt < 2; mt++)
#pragma unroll
        for (int nt = 0; nt < 4; nt++)
#pragma unroll
            for (int q = 0; q < 4; q++) acc2[mt][nt][q] = 0.0f;

    // zero xs pad cols 25..35 and xa pad cols 100..127
#pragma unroll
    for (int cpd = 25; cpd < 36; cpd++) sm->xs[tid * 36 + cpd] = 0u;
    for (int i = tid; i < 64 * 28; i += 256) {
        int r = i / 28, c2 = i % 28;
        sm->xa[r * 128 + 100 + c2] = 0u;
    }

    // load x tile -> xs (tf32): row m=(c*4+tl), col v
    {
        const float* xbase = x + (size_t)n * (C_ * TV_) + t0 * 25;
        int m = tid / 25, v = tid % 25;
#pragma unroll
        for (int it = 0; it < 25; it++) {
            int off = (m >> 2) * TV_ + (m & 3) * 25 + v;
            sm->xs[m * 36 + v] = f2tf32(xbase[off]);
            m += 10; v += 6;
            if (v >= 25) { v -= 25; m += 1; }
        }
    }

    const float* adg = g_adapt + n * (S_ * V_ * V_);

    for (int s = 0; s < 3; s++) {
        __syncthreads();     // prev stage2 reads of xa done; ads/wdt rewritable
        for (int i = tid; i < 1280; i += 256) {
            int v = i / 40, w = i % 40;
            float val = (v < 25 && w < 25) ? adg[(s * 25 + v) * 25 + w] : 0.0f;
            sm->ads[i] = f2tf32(val);
        }
        for (int i = tid; i < 4096; i += 256) {
            int c = i >> 6, o = i & 63;
            sm->wdt[c * 72 + o] = g_WdTt[(s * 64 + c) * 64 + o];
        }
        __syncthreads();

        // stage1: acc1 = x_tile @ adapt_s   (k4-validated pattern)
        float acc1[2][4][4];
#pragma unroll
        for (int mt = 0; mt < 2; mt++)
#pragma unroll
            for (int nt = 0; nt < 4; nt++)
#pragma unroll
                for (int q = 0; q < 4; q++) acc1[mt][nt][q] = 0.0f;
#pragma unroll
        for (int ks = 0; ks < 4; ks++) {
            const int kb = ks * 8;
            unsigned af[2][4], bf[4][2];
#pragma unroll
            for (int mt = 0; mt < 2; mt++) {
                int mB = mA0 + mt * 16;
                af[mt][0] = sm->xs[(mB + g) * 36 + kb + tig];
                af[mt][1] = sm->xs[(mB + g + 8) * 36 + kb + tig];
                af[mt][2] = sm->xs[(mB + g) * 36 + kb + tig + 4];
                af[mt][3] = sm->xs[(mB + g + 8) * 36 + kb + tig + 4];
            }
#pragma unroll
            for (int nt = 0; nt < 4; nt++) {
                bf[nt][0] = sm->ads[(kb + tig) * 40 + nt * 8 + g];
                bf[nt][1] = sm->ads[(kb + tig + 4) * 40 + nt * 8 + g];
            }
#pragma unroll
            for (int mt = 0; mt < 2; mt++)
#pragma unroll
                for (int nt = 0; nt < 4; nt++)
                    mma8(acc1[mt][nt], af[mt], bf[nt]);
        }
        // write xa[c][tl*25+w] = acc1 (tf32)
#pragma unroll
        for (int mt = 0; mt < 2; mt++) {
#pragma unroll
            for (int h = 0; h < 2; h++) {
                int row = mA0 + mt * 16 + g + h * 8;
                int c = row >> 2, tl = row & 3;
#pragma unroll
                for (int nt = 0; nt < 4; nt++) {
#pragma unroll
                    for (int e = 0; e < 2; e++) {
                        int w = nt * 8 + tig * 2 + e;
                        if (w < 25)
                            sm->xa[c * 128 + tl * 25 + w] = f2tf32(acc1[mt][nt][h * 2 + e]);
                    }
                }
            }
        }
        __syncthreads();

        // stage2: acc2 += wdT_s @ xa   (kg-validated [k][m]/[k][n] pattern)
#pragma unroll
        for (int ks = 0; ks < 8; ks++) {
            const int kb = ks * 8;
            unsigned a2[2][4], b2[4][2];
#pragma unroll
            for (int mt = 0; mt < 2; mt++) {
                int mB = mB0 + mt * 16;
                a2[mt][0] = sm->wdt[(kb + tig) * 72 + mB + g];
                a2[mt][1] = sm->wdt[(kb + tig) * 72 + mB + g + 8];
                a2[mt][2] = sm->wdt[(kb + tig + 4) * 72 + mB + g];
                a2[mt][3] = sm->wdt[(kb + tig + 4) * 72 + mB + g + 8];
            }
#pragma unroll
            for (int nt = 0; nt < 4; nt++) {
                int nB = nB0 + nt * 8;
                b2[nt][0] = sm->xa[(kb + tig) * 128 + nB + g];
                b2[nt][1] = sm->xa[(kb + tig + 4) * 128 + nB + g];
            }
#pragma unroll
            for (int mt = 0; mt < 2; mt++)
#pragma unroll
                for (int nt = 0; nt < 4; nt++)
                    mma8(acc2[mt][nt], a2[mt], b2[nt]);
        }
    }
    __syncthreads();

    // stage y (with bias) into ys (aliases xa)
    float* ys = (float*)sm->xa;
#pragma unroll
    for (int mt = 0; mt < 2; mt++) {
#pragma unroll
        for (int h = 0; h < 2; h++) {
            int o = mB0 + mt * 16 + g + h * 8;
            float bias = g_bdsum[o];
#pragma unroll
            for (int nt = 0; nt < 4; nt++) {
#pragma unroll
                for (int e = 0; e < 2; e++) {
                    int col = nB0 + nt * 8 + tig * 2 + e;
                    if (col < 100) ys[o * 100 + col] = acc2[mt][nt][h * 2 + e] + bias;
                }
            }
        }
    }
    __syncthreads();

    // BN partials: thread tid owns ys[tid*25 .. +25) (inside one o-row; o = tid/4)
    {
        float s1 = 0.f, s2 = 0.f;
        const float* p = ys + tid * 25;
#pragma unroll
        for (int j = 0; j < 25; j++) { float v = p[j]; s1 += v; s2 = fmaf(v, v, s2); }
        sm->rb1[tid] = s1; sm->rb2[tid] = s2;
    }
    __syncthreads();
    if (tid < 64) {
        int o = tid;
        float s1 = sm->rb1[o * 4] + sm->rb1[o * 4 + 1] + sm->rb1[o * 4 + 2] + sm->rb1[o * 4 + 3];
        float s2 = sm->rb2[o * 4] + sm->rb2[o * 4 + 1] + sm->rb2[o * 4 + 2] + sm->rb2[o * 4 + 3];
        g_pb[(size_t)bi * 128 + o * 2]     = s1;
        g_pb[(size_t)bi * 128 + o * 2 + 1] = s2;
    }

    // write y: row o -> g_y[n][o][t0*25 .. +100)
    float* ydst = g_y + (size_t)n * 480000 + t0 * 25;
    for (int i4 = tid; i4 < 1600; i4 += 256) {
        int o = i4 / 25, r = i4 % 25;
        *(float4*)(ydst + (size_t)o * TV_ + r * 4) = *(float4*)&ys[o * 100 + r * 4];
    }
}

// ---------------- K5b: reduce block partials -> scale/shift ----------------
__global__ __launch_bounds__(256) void k5b(const float* __restrict__ gamma,
                                           const float* __restrict__ beta) {
    __shared__ float r1[256], r2[256];
    const int c = blockIdx.x;
    const int tid = threadIdx.x;
    float s1 = 0.f, s2 = 0.f;
    for (int bi = tid; bi < 4800; bi += 256) {
        s1 += g_pb[(size_t)bi * 128 + c * 2];
        s2 += g_pb[(size_t)bi * 128 + c * 2 + 1];
    }
    r1[tid] = s1; r2[tid] = s2;
    __syncthreads();
    for (int off = 128; off > 0; off >>= 1) {
        if (tid < off) { r1[tid] += r1[tid + off]; r2[tid] += r2[tid + off]; }
        __syncthreads();
    }
    if (tid == 0) {
        double mean = (double)r1[0] / NTV_;
        double var = (double)r2[0] / NTV_ - mean * mean;
        float sc = gamma[c] * rsqrtf((float)var + 1e-5f);
        g_scale[c] = sc;
        g_shift[c] = beta[c] - (float)mean * sc;
    }
}

// ---------------- K6: BN apply + residual + relu ----------------
__global__ __launch_bounds__(256) void k6(const float* __restrict__ x, float* __restrict__ out) {
    size_t i = ((size_t)blockIdx.x * 256 + threadIdx.x) * 4;
    if (i >= (size_t)N_ * C_ * TV_) return;
    int c = (int)((i / TV_) & 63);
    float sc = g_scale[c], sh = g_shift[c];
    float4 yv = *(const float4*)&g_y[i];
    float4 xv = *(const float4*)&x[i];
    float4 o;
    o.x = fmaxf(fmaf(yv.x, sc, sh) + xv.x, 0.f);
    o.y = fmaxf(fmaf(yv.y, sc, sh) + xv.y, 0.f);
    o.z = fmaxf(fmaf(yv.z, sc, sh) + xv.z, 0.f);
    o.w = fmaxf(fmaf(yv.w, sc, sh) + xv.w, 0.f);
    *(float4*)&out[i] = o;
}

// ---------------- launch ----------------
extern "C" void kernel_launch(void* const* d_in, const int* in_sizes, int n_in,
                              void* d_out, int out_size) {
    const float* x     = (const float*)d_in[0];
    const float* Aad   = (const float*)d_in[1];
    const float* Wad   = (const float*)d_in[2];
    const float* wa    = (const float*)d_in[3];
    const float* ba    = (const float*)d_in[4];
    const float* wb    = (const float*)d_in[5];
    const float* bb    = (const float*)d_in[6];
    const float* wd    = (const float*)d_in[7];
    const float* bd    = (const float*)d_in[8];
    const float* gamma = (const float*)d_in[9];
    const float* beta  = (const float*)d_in[10];
    float* out = (float*)d_out;

    static bool attr_set = false;
    if (!attr_set) {
        cudaFuncSetAttribute(k45, cudaFuncAttributeMaxDynamicSharedMemorySize,
                             (int)sizeof(SmemK45));
        attr_set = true;
    }

    k0_pack<<<122, 256>>>(wa, ba, wb, bb, wd, bd);
    kg_tf32<<<dim3(1, 59, 64), 256>>>(x);
    k2a<<<dim3(3, 64, 5), 256>>>();
    k2b<<<dim3(3, 64), 640>>>(Aad, Wad);
    k45<<<4800, 256, sizeof(SmemK45)>>>(x);
    k5b<<<64, 256>>>(gamma, beta);
    k6<<<30000, 256>>>(x, out);
}

// round 10
// speedup vs baseline: 1.0545x; 1.0545x over previous
#include <cuda_runtime.h>
#include <math.h>

#define N_ 64
#define C_ 64
#define T_ 300
#define V_ 25
#define S_ 3
#define I_ 16
#define TV_ 7500
#define KIT_ 4800
#define NTV_ 480000.0

// ---------------- scratch ----------------
__device__ __align__(16) unsigned g_Wt[96 * 64];      // wa/wb packed, tf32 bits
__device__ __align__(16) unsigned g_WdTt[192 * 64];   // wdT: [(s*64+c)*64+o], tf32 bits
__device__ float g_bias[96];
__device__ float g_bdsum[64];
__device__ __align__(16) float g_a[(size_t)N_ * 48 * TV_];
__device__ __align__(16) float g_b[(size_t)N_ * 48 * TV_];
__device__ float g_psc[3 * 64 * 5 * 676];
__device__ float g_adapt[N_ * S_ * V_ * V_];
__device__ __align__(16) float g_y[(size_t)N_ * C_ * TV_];
__device__ float g_pb[4800 * 128];
__device__ float g_scale[64];
__device__ float g_shift[64];

__device__ __forceinline__ unsigned f2tf32(float f) {
    unsigned u; asm("cvt.rna.tf32.f32 %0, %1;" : "=r"(u) : "f"(f)); return u;
}
__device__ __forceinline__ void mma8(float* d, const unsigned* a, const unsigned* b) {
    asm volatile("mma.sync.aligned.m16n8k8.row.col.f32.tf32.tf32.f32 "
        "{%0,%1,%2,%3}, {%4,%5,%6,%7}, {%8,%9}, {%0,%1,%2,%3};"
        : "+f"(d[0]), "+f"(d[1]), "+f"(d[2]), "+f"(d[3])
        : "r"(a[0]), "r"(a[1]), "r"(a[2]), "r"(a[3]), "r"(b[0]), "r"(b[1]));
}

// ---------------- K0: pack ----------------
__global__ void k0_pack(const float* __restrict__ wa, const float* __restrict__ ba,
                        const float* __restrict__ wb, const float* __restrict__ bb,
                        const float* __restrict__ wd, const float* __restrict__ bd) {
    int idx = blockIdx.x * 256 + threadIdx.x;
    if (idx < 96 * 64) {
        int row = idx / 64, k = idx % 64;
        float v = (row < 48) ? wa[row * 64 + k] : wb[(row - 48) * 64 + k];
        g_Wt[idx] = f2tf32(v);
    } else if (idx < 96 * 64 + 192 * 64) {
        int j = idx - 96 * 64;
        int s = j / 4096, r = j % 4096;
        int c = r >> 6, o = r & 63;
        g_WdTt[j] = f2tf32(wd[(s * 64 + o) * 64 + c]);
    } else if (idx < 96 * 64 + 192 * 64 + 96) {
        int row = idx - (96 * 64 + 192 * 64);
        g_bias[row] = (row < 48) ? ba[row] : bb[row - 48];
    } else if (idx < 96 * 64 + 192 * 64 + 96 + 64) {
        int o = idx - (96 * 64 + 192 * 64 + 96);
        g_bdsum[o] = bd[o] + bd[64 + o] + bd[128 + o];
    }
}

// ---------------- KG: tf32 GEMM [96,64]@[64,7500] per n (a,b only) ----------------
#define PM 104
#define PN 136

__global__ __launch_bounds__(256) void kg_tf32(const float* __restrict__ x) {
    __shared__ __align__(16) unsigned As[32 * PM];
    __shared__ __align__(16) unsigned Bs[32 * PN];
    const int n = blockIdx.z;
    const int col0 = blockIdx.y * 128;
    const int t = threadIdx.x;
    const int warp = t >> 5, lane = t & 31;
    const int g = lane >> 2, tig = lane & 3;
    const int wm = warp >> 2, wn = warp & 3;
    const int mBase0 = wm * 48, nBase0 = wn * 32;
    const float* xn = x + (size_t)n * (C_ * TV_);

    float acc[3][4][4];
#pragma unroll
    for (int mt = 0; mt < 3; mt++)
#pragma unroll
        for (int nt = 0; nt < 4; nt++)
#pragma unroll
            for (int q = 0; q < 4; q++) acc[mt][nt][q] = 0.0f;

    for (int phase = 0; phase < 2; phase++) {
        const int kb0 = phase * 32;
#pragma unroll
        for (int it = 0; it < 3; it++) {
            int idx = it * 256 + t;
            int m = idx % 96;
            int kq = idx / 96;
            uint4 w4 = *(const uint4*)(g_Wt + m * 64 + kb0 + kq * 4);
            As[(kq * 4 + 0) * PM + m] = w4.x;
            As[(kq * 4 + 1) * PM + m] = w4.y;
            As[(kq * 4 + 2) * PM + m] = w4.z;
            As[(kq * 4 + 3) * PM + m] = w4.w;
        }
#pragma unroll
        for (int it = 0; it < 4; it++) {
            int idx = it * 256 + t;
            int k = idx >> 5;
            int c4 = (idx & 31) * 4;
            int col = col0 + c4;
            float4 v = make_float4(0.f, 0.f, 0.f, 0.f);
            if (col + 3 < TV_)
                v = *(const float4*)(xn + (size_t)(kb0 + k) * TV_ + col);
            unsigned* dst = &Bs[k * PN + c4];
            dst[0] = f2tf32(v.x); dst[1] = f2tf32(v.y);
            dst[2] = f2tf32(v.z); dst[3] = f2tf32(v.w);
        }
        __syncthreads();
#pragma unroll
        for (int ks = 0; ks < 4; ks++) {
            const int kb = ks * 8;
            unsigned a[3][4], b[4][2];
#pragma unroll
            for (int mt = 0; mt < 3; mt++) {
                int mB = mBase0 + mt * 16;
                a[mt][0] = As[(kb + tig) * PM + mB + g];
                a[mt][1] = As[(kb + tig) * PM + mB + g + 8];
                a[mt][2] = As[(kb + tig + 4) * PM + mB + g];
                a[mt][3] = As[(kb + tig + 4) * PM + mB + g + 8];
            }
#pragma unroll
            for (int nt = 0; nt < 4; nt++) {
                int nB = nBase0 + nt * 8;
                b[nt][0] = Bs[(kb + tig) * PN + nB + g];
                b[nt][1] = Bs[(kb + tig + 4) * PN + nB + g];
            }
#pragma unroll
            for (int mt = 0; mt < 3; mt++)
#pragma unroll
                for (int nt = 0; nt < 4; nt++)
                    mma8(acc[mt][nt], a[mt], b[nt]);
        }
        __syncthreads();
    }

#pragma unroll
    for (int mt = 0; mt < 3; mt++) {
#pragma unroll
        for (int h = 0; h < 2; h++) {
            int gm = mBase0 + mt * 16 + g + h * 8;
            float bias = g_bias[gm];
            float* dst = (gm < 48) ? (g_a + ((size_t)n * 48 + gm) * TV_)
                                   : (g_b + ((size_t)n * 48 + (gm - 48)) * TV_);
#pragma unroll
            for (int nt = 0; nt < 4; nt++) {
                int col = col0 + nBase0 + nt * 8 + tig * 2;
                if (col < TV_) {
                    float2 v = make_float2(acc[mt][nt][h * 2 + 0] + bias,
                                           acc[mt][nt][h * 2 + 1] + bias);
                    *(float2*)(dst + col) = v;
                }
            }
        }
    }
}

// ---------------- K2a: partial scores, dense 16x16 thread tiling ----------------
#define K2W 32
__global__ __launch_bounds__(256) void k2a() {
    __shared__ __align__(16) float ach[64 * K2W];
    __shared__ __align__(16) float bch[64 * K2W];
    const int s = blockIdx.x, n = blockIdx.y, q = blockIdx.z;
    const int tid = threadIdx.x;
    const float* abase = g_a + ((size_t)n * 48 + s * 16) * TV_;
    const float* bbase = g_b + ((size_t)n * 48 + s * 16) * TV_;
    const int v0 = 2 * (tid >> 4), w0 = 2 * (tid & 15);
    float acc00 = 0.f, acc01 = 0.f, acc10 = 0.f, acc11 = 0.f;

    for (int c = q * 15; c < q * 15 + 15; c++) {
        __syncthreads();
        for (int idx = tid; idx < 64 * 32; idx += 256) {
            int kk = idx >> 5, vv = idx & 31;
            int k = c * 64 + kk;
            int i = k / 300, tt = k % 300;
            float av = 0.f, bv = 0.f;
            if (vv < 25) {
                size_t off = (size_t)i * TV_ + tt * 25 + vv;
                av = abase[off]; bv = bbase[off];
            }
            ach[idx] = av;
            bch[idx] = bv;
        }
        __syncthreads();
#pragma unroll 8
        for (int kk = 0; kk < 64; kk++) {
            float2 a2 = *(const float2*)&ach[kk * K2W + v0];
            float2 b2 = *(const float2*)&bch[kk * K2W + w0];
            acc00 = fmaf(a2.x, b2.x, acc00);
            acc01 = fmaf(a2.x, b2.y, acc01);
            acc10 = fmaf(a2.y, b2.x, acc10);
            acc11 = fmaf(a2.y, b2.y, acc11);
        }
    }
    float* dst = g_psc + ((size_t)(s * 64 + n) * 5 + q) * 676;
    if (v0 < 25) {
        if (w0 < 25)     dst[v0 * 26 + w0]     = acc00;
        if (w0 + 1 < 25) dst[v0 * 26 + w0 + 1] = acc01;
    }
    if (v0 + 1 < 25) {
        if (w0 < 25)     dst[(v0 + 1) * 26 + w0]     = acc10;
        if (w0 + 1 < 25) dst[(v0 + 1) * 26 + w0 + 1] = acc11;
    }
}

// ---------------- K2b: combine + softmax + adapt (validated) ----------------
__global__ __launch_bounds__(640) void k2b(const float* __restrict__ Aad,
                                           const float* __restrict__ Wad) {
    __shared__ float ssc[25][26];
    __shared__ float smax[25];
    __shared__ float ssum[25];
    const int s = blockIdx.x, n = blockIdx.y;
    const int tid = threadIdx.x;
    const int v = tid / 25, w = tid % 25;
    const float* base = g_psc + (size_t)(s * 64 + n) * 5 * 676;

    if (tid < 625) {
        float sum = base[v * 26 + w];
        sum += base[676 + v * 26 + w];
        sum += base[2 * 676 + v * 26 + w];
        sum += base[3 * 676 + v * 26 + w];
        sum += base[4 * 676 + v * 26 + w];
        ssc[v][w] = sum * (1.0f / (float)KIT_);
    }
    __syncthreads();
    if (tid < 25) {
        float m = -1e30f;
        for (int vv = 0; vv < 25; vv++) m = fmaxf(m, ssc[vv][tid]);
        smax[tid] = m;
    }
    __syncthreads();
    if (tid < 625) ssc[v][w] = expf(ssc[v][w] - smax[w]);
    __syncthreads();
    if (tid < 25) {
        float sum = 0.0f;
        for (int vv = 0; vv < 25; vv++) sum += ssc[vv][tid];
        ssum[tid] = sum;
    }
    __syncthreads();
    if (tid < 625) {
        int aw = (s * 25 + v) * 25 + w;
        g_adapt[((n * 3 + s) * 25 + v) * 25 + w] = Aad[aw] + Wad[aw] + ssc[v][w] / ssum[w];
    }
}

// ---------------- K45: fused y = sum_s wdT_s @ (x @ adapt_s) + bd, BN partials ----------------
// x tile held in registers (loaded once, reused for all 3 s).
struct SmemK45 {
    unsigned xa[64 * 128];   // stage1 out / stage2 B: [k=c][n=tl*25+w]; aliased as ys
    unsigned ads[32 * 40];   // stage1 B: [k=v][n=w]
    unsigned wdt[64 * 72];   // stage2 A: [k=c][m=o]
    float rb1[256];
    float rb2[256];
};

__global__ __launch_bounds__(256) void k45(const float* __restrict__ x) {
    extern __shared__ __align__(16) unsigned char smraw[];
    SmemK45* sm = (SmemK45*)smraw;
    const int bi = blockIdx.x;
    const int n = bi / 75;
    const int t0 = (bi % 75) * 4;
    const int tid = threadIdx.x, warp = tid >> 5, lane = tid & 31;
    const int g = lane >> 2, tig = lane & 3;
    const int mA0 = warp * 32;
    const int mB0 = (warp >> 2) * 32;
    const int nB0 = (warp & 3) * 32;

    float acc2[2][4][4];
#pragma unroll
    for (int mt = 0; mt < 2; mt++)
#pragma unroll
        for (int nt = 0; nt < 4; nt++)
#pragma unroll
            for (int q = 0; q < 4; q++) acc2[mt][nt][q] = 0.0f;

    // zero xa pad cols 100..127
    for (int i = tid; i < 64 * 28; i += 256) {
        int r = i / 28, c2 = i % 28;
        sm->xa[r * 128 + 100 + c2] = 0u;
    }

    // x tile -> registers. Row ri<->(mt*2+h): row = mA0+g+ri*8; col ci<->(ks*2+j): v = ks*8+tig+j*4
    unsigned xr[4][8];
    {
        const float* xbase = x + (size_t)n * (C_ * TV_) + t0 * 25;
#pragma unroll
        for (int ri = 0; ri < 4; ri++) {
            int row = mA0 + g + ri * 8;
            const float* xrow = xbase + (size_t)(row >> 2) * TV_ + (row & 3) * 25;
#pragma unroll
            for (int ci = 0; ci < 8; ci++) {
                int v = (ci >> 1) * 8 + tig + (ci & 1) * 4;
                xr[ri][ci] = (v < 25) ? f2tf32(xrow[v]) : 0u;
            }
        }
    }

    const float* adg = g_adapt + n * (S_ * V_ * V_);

    for (int s = 0; s < 3; s++) {
        __syncthreads();     // prev stage2 reads of xa/ads/wdt done
        for (int i = tid; i < 1280; i += 256) {
            int v = i / 40, w = i % 40;
            float val = (v < 25 && w < 25) ? adg[(s * 25 + v) * 25 + w] : 0.0f;
            sm->ads[i] = f2tf32(val);
        }
        for (int i = tid; i < 4096; i += 256) {
            int c = i >> 6, o = i & 63;
            sm->wdt[c * 72 + o] = g_WdTt[(s * 64 + c) * 64 + o];
        }
        __syncthreads();

        // stage1: acc1 = x_tile @ adapt_s (A from registers)
        float acc1[2][4][4];
#pragma unroll
        for (int mt = 0; mt < 2; mt++)
#pragma unroll
            for (int nt = 0; nt < 4; nt++)
#pragma unroll
                for (int q = 0; q < 4; q++) acc1[mt][nt][q] = 0.0f;
#pragma unroll
        for (int ks = 0; ks < 4; ks++) {
            const int kb = ks * 8;
            unsigned af[2][4], bf[4][2];
#pragma unroll
            for (int mt = 0; mt < 2; mt++) {
                af[mt][0] = xr[mt * 2 + 0][ks * 2 + 0];
                af[mt][1] = xr[mt * 2 + 1][ks * 2 + 0];
                af[mt][2] = xr[mt * 2 + 0][ks * 2 + 1];
                af[mt][3] = xr[mt * 2 + 1][ks * 2 + 1];
            }
#pragma unroll
            for (int nt = 0; nt < 4; nt++) {
                bf[nt][0] = sm->ads[(kb + tig) * 40 + nt * 8 + g];
                bf[nt][1] = sm->ads[(kb + tig + 4) * 40 + nt * 8 + g];
            }
#pragma unroll
            for (int mt = 0; mt < 2; mt++)
#pragma unroll
                for (int nt = 0; nt < 4; nt++)
                    mma8(acc1[mt][nt], af[mt], bf[nt]);
        }
        // write xa[c][tl*25+w] = acc1 (tf32)
#pragma unroll
        for (int mt = 0; mt < 2; mt++) {
#pragma unroll
            for (int h = 0; h < 2; h++) {
                int row = mA0 + mt * 16 + g + h * 8;
                int c = row >> 2, tl = row & 3;
#pragma unroll
                for (int nt = 0; nt < 4; nt++) {
#pragma unroll
                    for (int e = 0; e < 2; e++) {
                        int w = nt * 8 + tig * 2 + e;
                        if (w < 25)
                            sm->xa[c * 128 + tl * 25 + w] = f2tf32(acc1[mt][nt][h * 2 + e]);
                    }
                }
            }
        }
        __syncthreads();

        // stage2: acc2 += wdT_s @ xa
#pragma unroll
        for (int ks = 0; ks < 8; ks++) {
            const int kb = ks * 8;
            unsigned a2[2][4], b2[4][2];
#pragma unroll
            for (int mt = 0; mt < 2; mt++) {
                int mB = mB0 + mt * 16;
                a2[mt][0] = sm->wdt[(kb + tig) * 72 + mB + g];
                a2[mt][1] = sm->wdt[(kb + tig) * 72 + mB + g + 8];
                a2[mt][2] = sm->wdt[(kb + tig + 4) * 72 + mB + g];
                a2[mt][3] = sm->wdt[(kb + tig + 4) * 72 + mB + g + 8];
            }
#pragma unroll
            for (int nt = 0; nt < 4; nt++) {
                int nB = nB0 + nt * 8;
                b2[nt][0] = sm->xa[(kb + tig) * 128 + nB + g];
                b2[nt][1] = sm->xa[(kb + tig + 4) * 128 + nB + g];
            }
#pragma unroll
            for (int mt = 0; mt < 2; mt++)
#pragma unroll
                for (int nt = 0; nt < 4; nt++)
                    mma8(acc2[mt][nt], a2[mt], b2[nt]);
        }
    }
    __syncthreads();

    float* ys = (float*)sm->xa;
#pragma unroll
    for (int mt = 0; mt < 2; mt++) {
#pragma unroll
        for (int h = 0; h < 2; h++) {
            int o = mB0 + mt * 16 + g + h * 8;
            float bias = g_bdsum[o];
#pragma unroll
            for (int nt = 0; nt < 4; nt++) {
#pragma unroll
                for (int e = 0; e < 2; e++) {
                    int col = nB0 + nt * 8 + tig * 2 + e;
                    if (col < 100) ys[o * 100 + col] = acc2[mt][nt][h * 2 + e] + bias;
                }
            }
        }
    }
    __syncthreads();

    {
        float s1 = 0.f, s2 = 0.f;
        const float* p = ys + tid * 25;
#pragma unroll
        for (int j = 0; j < 25; j++) { float v = p[j]; s1 += v; s2 = fmaf(v, v, s2); }
        sm->rb1[tid] = s1; sm->rb2[tid] = s2;
    }
    __syncthreads();
    if (tid < 64) {
        int o = tid;
        float s1 = sm->rb1[o * 4] + sm->rb1[o * 4 + 1] + sm->rb1[o * 4 + 2] + sm->rb1[o * 4 + 3];
        float s2 = sm->rb2[o * 4] + sm->rb2[o * 4 + 1] + sm->rb2[o * 4 + 2] + sm->rb2[o * 4 + 3];
        g_pb[(size_t)bi * 128 + o * 2]     = s1;
        g_pb[(size_t)bi * 128 + o * 2 + 1] = s2;
    }

    float* ydst = g_y + (size_t)n * 480000 + t0 * 25;
    for (int i4 = tid; i4 < 1600; i4 += 256) {
        int o = i4 / 25, r = i4 % 25;
        *(float4*)(ydst + (size_t)o * TV_ + r * 4) = *(float4*)&ys[o * 100 + r * 4];
    }
}

// ---------------- K5b: reduce block partials -> scale/shift ----------------
__global__ __launch_bounds__(256) void k5b(const float* __restrict__ gamma,
                                           const float* __restrict__ beta) {
    __shared__ float r1[256], r2[256];
    const int c = blockIdx.x;
    const int tid = threadIdx.x;
    float s1 = 0.f, s2 = 0.f;
    for (int bi = tid; bi < 4800; bi += 256) {
        s1 += g_pb[(size_t)bi * 128 + c * 2];
        s2 += g_pb[(size_t)bi * 128 + c * 2 + 1];
    }
    r1[tid] = s1; r2[tid] = s2;
    __syncthreads();
    for (int off = 128; off > 0; off >>= 1) {
        if (tid < off) { r1[tid] += r1[tid + off]; r2[tid] += r2[tid + off]; }
        __syncthreads();
    }
    if (tid == 0) {
        double mean = (double)r1[0] / NTV_;
        double var = (double)r2[0] / NTV_ - mean * mean;
        float sc = gamma[c] * rsqrtf((float)var + 1e-5f);
        g_scale[c] = sc;
        g_shift[c] = beta[c] - (float)mean * sc;
    }
}

// ---------------- K6: BN apply + residual + relu ----------------
__global__ __launch_bounds__(256) void k6(const float* __restrict__ x, float* __restrict__ out) {
    size_t i = ((size_t)blockIdx.x * 256 + threadIdx.x) * 4;
    if (i >= (size_t)N_ * C_ * TV_) return;
    int c = (int)((i / TV_) & 63);
    float sc = g_scale[c], sh = g_shift[c];
    float4 yv = *(const float4*)&g_y[i];
    float4 xv = *(const float4*)&x[i];
    float4 o;
    o.x = fmaxf(fmaf(yv.x, sc, sh) + xv.x, 0.f);
    o.y = fmaxf(fmaf(yv.y, sc, sh) + xv.y, 0.f);
    o.z = fmaxf(fmaf(yv.z, sc, sh) + xv.z, 0.f);
    o.w = fmaxf(fmaf(yv.w, sc, sh) + xv.w, 0.f);
    *(float4*)&out[i] = o;
}

// ---------------- launch ----------------
extern "C" void kernel_launch(void* const* d_in, const int* in_sizes, int n_in,
                              void* d_out, int out_size) {
    const float* x     = (const float*)d_in[0];
    const float* Aad   = (const float*)d_in[1];
    const float* Wad   = (const float*)d_in[2];
    const float* wa    = (const float*)d_in[3];
    const float* ba    = (const float*)d_in[4];
    const float* wb    = (const float*)d_in[5];
    const float* bb    = (const float*)d_in[6];
    const float* wd    = (const float*)d_in[7];
    const float* bd    = (const float*)d_in[8];
    const float* gamma = (const float*)d_in[9];
    const float* beta  = (const float*)d_in[10];
    float* out = (float*)d_out;

    static bool attr_set = false;
    if (!attr_set) {
        cudaFuncSetAttribute(k45, cudaFuncAttributeMaxDynamicSharedMemorySize,
                             (int)sizeof(SmemK45));
        attr_set = true;
    }

    k0_pack<<<122, 256>>>(wa, ba, wb, bb, wd, bd);
    kg_tf32<<<dim3(1, 59, 64), 256>>>(x);
    k2a<<<dim3(3, 64, 5), 256>>>();
    k2b<<<dim3(3, 64), 640>>>(Aad, Wad);
    k45<<<4800, 256, sizeof(SmemK45)>>>(x);
    k5b<<<64, 256>>>(gamma, beta);
    k6<<<30000, 256>>>(x, out);
}